// round 14
// baseline (speedup 1.0000x reference)
#include <cuda_runtime.h>
#include <cuda_fp16.h>
#include <cstdint>

#define BATCH 8
#define SEQ   2048
#define DIM   128
#define BQ    64               // queries per CTA (4 warps x 16 rows)
#define BK    32               // keys per inner tile (double-buffered)
#define NT    128
#define QT    (SEQ / BQ)       // 32
#define SPLITK 512
#define MAXSPL (SEQ / SPLITK)  // 4

// strides (32-bit words)
#define KBSTR 68    // fp16 K rows: 64 u32 payload (banks 4g+qd distinct)
#define V2STR 136   // V fp16-pair rows (banks 8qd+g distinct)
#define P2STR 36    // per-warp P fp16-pair rows
#define QSTGS 132   // Q fp32 staging stride

// smem: stage = K(32*68) + V2(16*136) = 4352 words
#define STG   4352
#define KHo   0
#define V2o   (32 * KBSTR)            // 2176
#define P2w   (2 * STG)               // 8704
#define SMEM_WORDS (P2w + 4 * 16 * P2STR)  // 11008
#define SMEM_BYTES (SMEM_WORDS * 4)        // 44032 -> 4 CTAs/SM

// ---- scratch ----
__device__ alignas(16) uint32_t g_k2[BATCH][SEQ][64];        // half2 dim-pairs
__device__ alignas(16) uint32_t g_v2[BATCH][SEQ / 2][DIM];   // half2 key-pairs
__device__ float g_partial[BATCH][16][DIM];
__device__ alignas(16) __half g_pOh[BATCH][QT][MAXSPL][BQ][DIM];
__device__ float g_pl[BATCH][QT][MAXSPL][BQ];
__device__ int   g_cnt[BATCH][QT];    // zero-init; self-resetting

// ---- helpers ----
__device__ __forceinline__ uint32_t smem_u32(const void* p) {
    uint32_t a;
    asm("{ .reg .u64 t; cvta.to.shared.u64 t, %1; cvt.u32.u64 %0, t; }"
        : "=r"(a) : "l"(p));
    return a;
}
__device__ __forceinline__ void mma_fp16(float* c, const uint32_t* a,
                                         uint32_t b0, uint32_t b1) {
    asm volatile(
        "mma.sync.aligned.m16n8k16.row.col.f32.f16.f16.f32 "
        "{%0,%1,%2,%3}, {%4,%5,%6,%7}, {%8,%9}, {%0,%1,%2,%3};"
        : "+f"(c[0]), "+f"(c[1]), "+f"(c[2]), "+f"(c[3])
        : "r"(a[0]), "r"(a[1]), "r"(a[2]), "r"(a[3]), "r"(b0), "r"(b1));
}
#define CP_ASYNC16F(dst, src) \
    asm volatile("cp.async.ca.shared.global [%0], [%1], 16;" \
                 :: "r"(dst), "l"(src) : "memory")
#define CP_COMMIT() asm volatile("cp.async.commit_group;" ::: "memory")

// ---- prep: K -> fp16 dim-pairs; V -> fp16 key-pairs; V chunk sums ----
__global__ void __launch_bounds__(256)
prep_kernel(const float* __restrict__ k, const float* __restrict__ v) {
    const int b = blockIdx.y, x = blockIdx.x, tid = threadIdx.x;
    if (x < 64) {
        // K convert: rows [32x, 32x+32)
        const float* kb = k + ((size_t)b * SEQ + 32 * x) * DIM;
#pragma unroll
        for (int i = 0; i < 4; ++i) {
            int idx = tid + i * 256;      // 32 rows x 32 float4
            int r = idx >> 5, c4 = idx & 31;
            float4 t = ((const float4*)(kb + (size_t)r * DIM))[c4];
            __half2 h01 = __floats2half2_rn(t.x, t.y);
            __half2 h23 = __floats2half2_rn(t.z, t.w);
            *(uint2*)&g_k2[b][32 * x + r][c4 * 2] =
                make_uint2(*(uint32_t*)&h01, *(uint32_t*)&h23);
        }
    } else if (x < 96) {
        // V pairs: keypairs [32(x-64), +32)
        int kp0 = 32 * (x - 64);
        const float* vb = v + ((size_t)b * SEQ + 2 * kp0) * DIM;
#pragma unroll
        for (int i = 0; i < 4; ++i) {
            int idx = tid + i * 256;      // 32 pairs x 32 float4-cols
            int kp = idx >> 5, c4 = idx & 31;
            float4 a = ((const float4*)(vb + (size_t)(2 * kp) * DIM))[c4];
            float4 c = ((const float4*)(vb + (size_t)(2 * kp + 1) * DIM))[c4];
            __half2 p0 = __floats2half2_rn(a.x, c.x);
            __half2 p1 = __floats2half2_rn(a.y, c.y);
            __half2 p2 = __floats2half2_rn(a.z, c.z);
            __half2 p3 = __floats2half2_rn(a.w, c.w);
            uint4 pk = make_uint4(*(uint32_t*)&p0, *(uint32_t*)&p1,
                                  *(uint32_t*)&p2, *(uint32_t*)&p3);
            *(uint4*)&g_v2[b][kp0 + kp][c4 * 4] = pk;
        }
    } else {
        // V chunk sums: chunk c = x - 96, rows [128c, 128c+128)
        __shared__ float vs[2][DIM];
        int c = x - 96;
        int d = tid & 127, h = tid >> 7;
        const float* vp = v + ((size_t)b * SEQ + 128 * c + 64 * h) * DIM + d;
        float s = 0.f;
#pragma unroll 8
        for (int r = 0; r < 64; ++r) s += vp[(size_t)r * DIM];
        vs[h][d] = s;
        __syncthreads();
        if (tid < DIM) g_partial[b][c][tid] = vs[0][tid] + vs[1][tid];
    }
}

// ---- fp16 flash attention + fused split-K combine ----
__global__ void __launch_bounds__(NT, 4)
attn_kernel(const float* __restrict__ q, const int* __restrict__ elen,
            float* __restrict__ out) {
    extern __shared__ float sm[];
    __shared__ alignas(16) float mvv[DIM];   // 16B-aligned (float4 casts!)
    __shared__ int s_last;

    const int b    = blockIdx.y;
    const int qt   = blockIdx.x;
    const int spl  = blockIdx.z;
    const int q0   = qt * BQ;
    const int L    = elen[b];
    const int kbeg = spl * SPLITK;
    const int tid  = threadIdx.x;
    const int wid  = tid >> 5;
    const int lane = tid & 31;
    const int g    = lane >> 2;
    const int qd   = lane & 3;

    // mean(V) writer for fully-masked q-tiles (spl 0 owns them)
    if (q0 >= L) {
        if (spl == 0) {
            if (tid < DIM) {
                float s = 0.f;
#pragma unroll
                for (int c = 0; c < 16; ++c) s += g_partial[b][c][tid];
                mvv[tid] = s * (1.0f / SEQ);
            }
            __syncthreads();
            float* ob = out + ((size_t)b * SEQ + q0) * DIM;
#pragma unroll
            for (int i = 0; i < 16; ++i) {
                int idx = tid + i * NT;   // 64 rows x 32 float4
                int r = idx >> 5, c4 = idx & 31;
                *(float4*)&ob[(size_t)r * DIM + c4 * 4] = *(float4*)&mvv[c4 * 4];
            }
        }
        return;
    }
    if (kbeg >= L) return;

    const int kend = min(kbeg + SPLITK, L);
    const int ntiles = (kend - kbeg + BK - 1) / BK;
    const int nspl   = (L + SPLITK - 1) / SPLITK;

    const uint32_t sbase = smem_u32(sm);
    const float* qb = q + ((size_t)b * SEQ + q0) * DIM;

    // ---- stage Q fp32 (scaled)
    const float scale = 0.08838834764831845f;
#pragma unroll
    for (int i = 0; i < 16; ++i) {
        int idx = tid + i * NT;
        int r = idx >> 5, c4 = idx & 31;
        float4 t = ((const float4*)(qb + (size_t)r * DIM))[c4];
        t.x *= scale; t.y *= scale; t.z *= scale; t.w *= scale;
        *(float4*)&sm[r * QSTGS + c4 * 4] = t;
    }
    __syncthreads();

    // ---- resident fp16 Q fragments
    uint32_t Qh[8][4];
    {
        const int r0 = wid * 16 + g;
        const float* row0 = &sm[r0 * QSTGS];
        const float* row1 = &sm[(r0 + 8) * QSTGS];
#pragma unroll
        for (int kc = 0; kc < 8; ++kc) {
            int c = kc * 16 + 2 * qd;
            __half2 a0 = __floats2half2_rn(row0[c],     row0[c + 1]);
            __half2 a1 = __floats2half2_rn(row1[c],     row1[c + 1]);
            __half2 a2 = __floats2half2_rn(row0[c + 8], row0[c + 9]);
            __half2 a3 = __floats2half2_rn(row1[c + 8], row1[c + 9]);
            Qh[kc][0] = *(uint32_t*)&a0;
            Qh[kc][1] = *(uint32_t*)&a1;
            Qh[kc][2] = *(uint32_t*)&a2;
            Qh[kc][3] = *(uint32_t*)&a3;
        }
    }
    __syncthreads();

    // ---- tile loader
    auto load_tile = [&](int st, int k0) {
        uint32_t base = sbase + 4 * (st * STG);
#pragma unroll
        for (int i = 0; i < 4; ++i) {
            int idx = tid + i * NT;
            int r = idx >> 4, c = idx & 15;
            CP_ASYNC16F(base + (uint32_t)(KHo + r * KBSTR + c * 4) * 4,
                        &g_k2[b][k0 + r][c * 4]);
        }
#pragma unroll
        for (int i = 0; i < 4; ++i) {
            int idx = tid + i * NT;
            int r = idx >> 5, c4 = idx & 31;
            CP_ASYNC16F(base + (uint32_t)(V2o + r * V2STR + c4 * 4) * 4,
                        &g_v2[b][(k0 >> 1) + r][c4 * 4]);
        }
    };

    load_tile(0, kbeg);
    CP_COMMIT();
    if (ntiles > 1) load_tile(1, kbeg + BK);
    CP_COMMIT();

    float o[16][4];
#pragma unroll
    for (int nc = 0; nc < 16; ++nc)
#pragma unroll
        for (int i = 0; i < 4; ++i) o[nc][i] = 0.f;
    float lsum0 = 0.f, lsum1 = 0.f;

    uint32_t* sp = (uint32_t*)&sm[P2w + wid * 16 * P2STR];

    for (int kt = 0; kt < ntiles; ++kt) {
        const int k0 = kbeg + kt * BK;
        const int st = kt & 1;
        if (kt + 1 < ntiles)
            asm volatile("cp.async.wait_group 1;" ::: "memory");
        else
            asm volatile("cp.async.wait_group 0;" ::: "memory");
        __syncthreads();

        const uint32_t* k2  = (const uint32_t*)&sm[st * STG + KHo];
        const uint32_t* sv2 = (const uint32_t*)&sm[st * STG + V2o];

        float s[4][4];
#pragma unroll
        for (int nc = 0; nc < 4; ++nc)
#pragma unroll
            for (int i = 0; i < 4; ++i) s[nc][i] = 0.f;
#pragma unroll
        for (int kc = 0; kc < 8; ++kc) {
#pragma unroll
            for (int nc = 0; nc < 4; ++nc) {
                int bse = (nc * 8 + g) * KBSTR + kc * 8 + qd;
                mma_fp16(s[nc], Qh[kc], k2[bse], k2[bse + 4]);
            }
        }

#pragma unroll
        for (int nc = 0; nc < 4; ++nc) {
            int c0 = k0 + nc * 8 + 2 * qd;
            bool v0 = c0 < kend, v1 = c0 + 1 < kend;
            float p0 = v0 ? __expf(s[nc][0]) : 0.f;
            float p1 = v1 ? __expf(s[nc][1]) : 0.f;
            float p2 = v0 ? __expf(s[nc][2]) : 0.f;
            float p3 = v1 ? __expf(s[nc][3]) : 0.f;
            __half2 h01 = __floats2half2_rn(p0, p1);
            __half2 h23 = __floats2half2_rn(p2, p3);
            float2 f01 = __half22float2(h01);
            float2 f23 = __half22float2(h23);
            lsum0 += f01.x + f01.y;
            lsum1 += f23.x + f23.y;
            sp[g * P2STR + nc * 4 + qd]       = *(uint32_t*)&h01;
            sp[(g + 8) * P2STR + nc * 4 + qd] = *(uint32_t*)&h23;
        }
        __syncwarp();

#pragma unroll
        for (int kc = 0; kc < 2; ++kc) {
            uint32_t A[4];
            A[0] = sp[g * P2STR + kc * 8 + qd];
            A[1] = sp[(g + 8) * P2STR + kc * 8 + qd];
            A[2] = sp[g * P2STR + kc * 8 + 4 + qd];
            A[3] = sp[(g + 8) * P2STR + kc * 8 + 4 + qd];
#pragma unroll
            for (int nc = 0; nc < 16; ++nc) {
                int col = nc * 8 + g;
                uint32_t b0 = sv2[(kc * 8 + qd) * V2STR + col];
                uint32_t b1 = sv2[(kc * 8 + 4 + qd) * V2STR + col];
                mma_fp16(o[nc], A, b0, b1);
            }
        }
        __syncthreads();

        if (kt + 2 < ntiles) {
            load_tile(st, k0 + 2 * BK);
            CP_COMMIT();
        }
    }

    // ---- epilogue ----
    lsum0 += __shfl_xor_sync(0xffffffffu, lsum0, 1);
    lsum0 += __shfl_xor_sync(0xffffffffu, lsum0, 2);
    lsum1 += __shfl_xor_sync(0xffffffffu, lsum1, 1);
    lsum1 += __shfl_xor_sync(0xffffffffu, lsum1, 2);

    const int r0 = wid * 16 + g;

    // mean(V) into aligned static shared (only when tile straddles L)
    const bool need_mean = (q0 + BQ > L);
    if (need_mean) {
        if (tid < DIM) {
            float s = 0.f;
#pragma unroll
            for (int c = 0; c < 16; ++c) s += g_partial[b][c][tid];
            mvv[tid] = s * (1.0f / SEQ);
        }
        __syncthreads();
    }

    if (nspl == 1) {
        // ---- direct write from registers (no partials) ----
        float inv0 = 1.0f / lsum0, inv1 = 1.0f / lsum1;
        bool m0 = (q0 + r0) >= L, m1 = (q0 + r0 + 8) >= L;
        float* o0p = out + ((size_t)b * SEQ + q0 + r0) * DIM;
        float* o1p = o0p + 8 * DIM;
#pragma unroll
        for (int nc = 0; nc < 16; ++nc) {
            int col = nc * 8 + 2 * qd;
            float2 w0 = m0 ? *(float2*)&mvv[col]
                           : make_float2(o[nc][0] * inv0, o[nc][1] * inv0);
            float2 w1 = m1 ? *(float2*)&mvv[col]
                           : make_float2(o[nc][2] * inv1, o[nc][3] * inv1);
            *(float2*)&o0p[col] = w0;
            *(float2*)&o1p[col] = w1;
        }
        return;
    }

    // ---- write partial O (fp16) + l ----
    {
        __half* o0 = &g_pOh[b][qt][spl][r0][0];
        __half* o1 = &g_pOh[b][qt][spl][r0 + 8][0];
#pragma unroll
        for (int nc = 0; nc < 16; ++nc) {
            __half2 a = __floats2half2_rn(o[nc][0], o[nc][1]);
            __half2 c = __floats2half2_rn(o[nc][2], o[nc][3]);
            *(__half2*)&o0[nc * 8 + 2 * qd] = a;
            *(__half2*)&o1[nc * 8 + 2 * qd] = c;
        }
        if (qd == 0) {
            g_pl[b][qt][spl][r0]     = lsum0;
            g_pl[b][qt][spl][r0 + 8] = lsum1;
        }
    }
    __threadfence();
    __syncthreads();

    if (tid == 0) {
        int old = atomicAdd(&g_cnt[b][qt], 1);
        s_last = (old == nspl - 1) ? 1 : 0;
        if (s_last) g_cnt[b][qt] = 0;   // self-reset for next replay
    }
    __syncthreads();
    if (!s_last) return;

    // ---- fused combine: this CTA sums all splits and writes output ----
    {
        const int r    = tid >> 1;          // 0..63
        const int dh   = (tid & 1) * 64;
        const int row  = q0 + r;
        float* op = out + ((size_t)b * SEQ + row) * DIM + dh;

        if (row >= L) {
#pragma unroll
            for (int j = 0; j < 16; ++j)
                *(float4*)&op[j * 4] = *(float4*)&mvv[dh + j * 4];
            return;
        }

        float lsum = 0.f;
        for (int s = 0; s < nspl; ++s) lsum += g_pl[b][qt][s][r];
        float inv = 1.0f / lsum;

#pragma unroll
        for (int h2 = 0; h2 < 2; ++h2) {
            float acc[32];
#pragma unroll
            for (int j = 0; j < 32; ++j) acc[j] = 0.f;
            for (int s = 0; s < nspl; ++s) {
                const uint4* po =
                    (const uint4*)(&g_pOh[b][qt][s][r][dh + 32 * h2]);
#pragma unroll
                for (int j = 0; j < 4; ++j) {
                    uint4 t = po[j];
                    float2 f0 = __half22float2(*(__half2*)&t.x);
                    float2 f1 = __half22float2(*(__half2*)&t.y);
                    float2 f2 = __half22float2(*(__half2*)&t.z);
                    float2 f3 = __half22float2(*(__half2*)&t.w);
                    acc[8*j+0] += f0.x; acc[8*j+1] += f0.y;
                    acc[8*j+2] += f1.x; acc[8*j+3] += f1.y;
                    acc[8*j+4] += f2.x; acc[8*j+5] += f2.y;
                    acc[8*j+6] += f3.x; acc[8*j+7] += f3.y;
                }
            }
#pragma unroll
            for (int j = 0; j < 8; ++j)
                *(float4*)&op[32 * h2 + j * 4] =
                    make_float4(acc[4*j] * inv, acc[4*j+1] * inv,
                                acc[4*j+2] * inv, acc[4*j+3] * inv);
        }
    }
}

extern "C" void kernel_launch(void* const* d_in, const int* in_sizes, int n_in,
                              void* d_out, int out_size) {
    const float* q  = (const float*)d_in[0];
    const float* k  = (const float*)d_in[1];
    const float* v  = (const float*)d_in[2];
    const int*   el = (const int*)d_in[3];
    float*       out = (float*)d_out;

    cudaFuncSetAttribute(attn_kernel,
                         cudaFuncAttributeMaxDynamicSharedMemorySize, SMEM_BYTES);

    prep_kernel<<<dim3(112, BATCH), 256>>>(k, v);
    attn_kernel<<<dim3(QT, BATCH, MAXSPL), NT, SMEM_BYTES>>>(q, el, out);
}

// round 15
// speedup vs baseline: 1.0720x; 1.0720x over previous
#include <cuda_runtime.h>
#include <cuda_fp16.h>
#include <cstdint>

#define BATCH 8
#define SEQ   2048
#define DIM   128
#define BQ    64               // queries per CTA (4 warps x 16 rows)
#define BK    32               // keys per inner tile (double-buffered)
#define NT    128
#define QT    (SEQ / BQ)       // 32
#define SPLITK 512
#define MAXSPL (SEQ / SPLITK)  // 4

// strides (32-bit words)
#define KBSTR 68    // fp16 K rows (16B-unit stride 17 -> LDSM conflict-free)
#define VTSTR 20    // fp16 V^T rows: 32 keys = 16 words + 4 pad (stride 5 mod 8)
#define P2STR 36    // per-warp P fp16-pair rows (stride 9 mod 8 = 1)
#define QSTGS 132   // Q fp32 staging stride

// smem: stage = K(32*68=2176) + VT(128*20=2560) = 4736 words
#define STG   4736
#define KHo   0
#define VTo   (32 * KBSTR)            // 2176
#define P2w   (2 * STG)               // 9472
#define SMEM_WORDS (P2w + 4 * 16 * P2STR)  // 11776
#define SMEM_BYTES (SMEM_WORDS * 4)        // 47104 -> 4 CTAs/SM (184 KB)

// ---- scratch ----
__device__ alignas(16) uint32_t g_k2[BATCH][SEQ][64];            // half2 dim-pairs
__device__ alignas(16) __half  g_vT[BATCH][SEQ / 32][DIM][32];   // V^T 32-key tiles
__device__ float g_partial[BATCH][16][DIM];
__device__ alignas(16) __half g_pOh[BATCH][QT][MAXSPL][BQ][DIM];
__device__ float g_pl[BATCH][QT][MAXSPL][BQ];

// ---- helpers ----
__device__ __forceinline__ uint32_t smem_u32(const void* p) {
    uint32_t a;
    asm("{ .reg .u64 t; cvta.to.shared.u64 t, %1; cvt.u32.u64 %0, t; }"
        : "=r"(a) : "l"(p));
    return a;
}
__device__ __forceinline__ void mma_fp16(float* c, const uint32_t* a,
                                         uint32_t b0, uint32_t b1) {
    asm volatile(
        "mma.sync.aligned.m16n8k16.row.col.f32.f16.f16.f32 "
        "{%0,%1,%2,%3}, {%4,%5,%6,%7}, {%8,%9}, {%0,%1,%2,%3};"
        : "+f"(c[0]), "+f"(c[1]), "+f"(c[2]), "+f"(c[3])
        : "r"(a[0]), "r"(a[1]), "r"(a[2]), "r"(a[3]), "r"(b0), "r"(b1));
}
#define LDSM_X4(r0, r1, r2, r3, addr) \
    asm volatile("ldmatrix.sync.aligned.m8n8.x4.shared.b16 {%0,%1,%2,%3}, [%4];" \
        : "=r"(r0), "=r"(r1), "=r"(r2), "=r"(r3) : "r"(addr))
#define CP_ASYNC16F(dst, src) \
    asm volatile("cp.async.ca.shared.global [%0], [%1], 16;" \
                 :: "r"(dst), "l"(src) : "memory")
#define CP_COMMIT() asm volatile("cp.async.commit_group;" ::: "memory")

// ---- prep: K -> fp16 dim-pairs; V -> transposed fp16 tiles; V chunk sums ----
__global__ void __launch_bounds__(256)
prep_kernel(const float* __restrict__ k, const float* __restrict__ v) {
    const int b = blockIdx.y, x = blockIdx.x, tid = threadIdx.x;
    if (x < 64) {
        // K convert: rows [32x, 32x+32)
        const float* kb = k + ((size_t)b * SEQ + 32 * x) * DIM;
#pragma unroll
        for (int i = 0; i < 4; ++i) {
            int idx = tid + i * 256;      // 32 rows x 32 float4
            int r = idx >> 5, c4 = idx & 31;
            float4 t = ((const float4*)(kb + (size_t)r * DIM))[c4];
            __half2 h01 = __floats2half2_rn(t.x, t.y);
            __half2 h23 = __floats2half2_rn(t.z, t.w);
            *(uint2*)&g_k2[b][32 * x + r][c4 * 2] =
                make_uint2(*(uint32_t*)&h01, *(uint32_t*)&h23);
        }
    } else if (x < 128) {
        // V^T tile t = x-64: 32 keys x 128 dims -> [dim][key] fp16
        __shared__ float stg[32][133];
        int t = x - 64;
        const float* vb = v + ((size_t)b * SEQ + 32 * t) * DIM;
#pragma unroll
        for (int i = 0; i < 4; ++i) {
            int idx = tid + i * 256;      // 32 rows x 32 float4
            int r = idx >> 5, c4 = idx & 31;
            float4 tt = ((const float4*)(vb + (size_t)r * DIM))[c4];
            stg[r][c4 * 4 + 0] = tt.x; stg[r][c4 * 4 + 1] = tt.y;
            stg[r][c4 * 4 + 2] = tt.z; stg[r][c4 * 4 + 3] = tt.w;
        }
        __syncthreads();
        int d = tid >> 1, kg = tid & 1;   // dim, 16-key group
        uint32_t u[8];
#pragma unroll
        for (int j = 0; j < 8; ++j) {
            __half2 h = __floats2half2_rn(stg[kg * 16 + 2 * j][d],
                                          stg[kg * 16 + 2 * j + 1][d]);
            u[j] = *(uint32_t*)&h;
        }
        uint4* dst = (uint4*)&g_vT[b][t][d][kg * 16];
        dst[0] = make_uint4(u[0], u[1], u[2], u[3]);
        dst[1] = make_uint4(u[4], u[5], u[6], u[7]);
    } else {
        // V chunk sums: chunk c = x - 128, rows [128c, 128c+128)
        __shared__ float vs[2][DIM];
        int c = x - 128;
        int d = tid & 127, h = tid >> 7;
        const float* vp = v + ((size_t)b * SEQ + 128 * c + 64 * h) * DIM + d;
        float s = 0.f;
#pragma unroll 8
        for (int r = 0; r < 64; ++r) s += vp[(size_t)r * DIM];
        vs[h][d] = s;
        __syncthreads();
        if (tid < DIM) g_partial[b][c][tid] = vs[0][tid] + vs[1][tid];
    }
}

// ---- fp16 flash attention (LDSM-fed), split-K partials ----
__global__ void __launch_bounds__(NT, 4)
attn_kernel(const float* __restrict__ q, const int* __restrict__ elen) {
    extern __shared__ float sm[];
    const int b    = blockIdx.y;
    const int qt   = blockIdx.x;
    const int spl  = blockIdx.z;
    const int q0   = qt * BQ;
    const int L    = elen[b];
    const int kbeg = spl * SPLITK;
    const int tid  = threadIdx.x;
    const int wid  = tid >> 5;
    const int lane = tid & 31;
    const int g    = lane >> 2;
    const int qd   = lane & 3;
    const int grp  = lane >> 3;   // ldmatrix matrix-group
    const int lr   = lane & 7;    // ldmatrix row-in-group

    if (q0 >= L || kbeg >= L) return;
    const int kend = min(kbeg + SPLITK, L);
    const int ntiles = (kend - kbeg + BK - 1) / BK;

    const uint32_t sbase = smem_u32(sm);
    const float* qb = q + ((size_t)b * SEQ + q0) * DIM;

    // ---- stage Q fp32 (scaled)
    const float scale = 0.08838834764831845f;
#pragma unroll
    for (int i = 0; i < 16; ++i) {
        int idx = tid + i * NT;
        int r = idx >> 5, c4 = idx & 31;
        float4 t = ((const float4*)(qb + (size_t)r * DIM))[c4];
        t.x *= scale; t.y *= scale; t.z *= scale; t.w *= scale;
        *(float4*)&sm[r * QSTGS + c4 * 4] = t;
    }
    __syncthreads();

    // ---- resident fp16 Q fragments
    uint32_t Qh[8][4];
    {
        const int r0 = wid * 16 + g;
        const float* row0 = &sm[r0 * QSTGS];
        const float* row1 = &sm[(r0 + 8) * QSTGS];
#pragma unroll
        for (int kc = 0; kc < 8; ++kc) {
            int c = kc * 16 + 2 * qd;
            __half2 a0 = __floats2half2_rn(row0[c],     row0[c + 1]);
            __half2 a1 = __floats2half2_rn(row1[c],     row1[c + 1]);
            __half2 a2 = __floats2half2_rn(row0[c + 8], row0[c + 9]);
            __half2 a3 = __floats2half2_rn(row1[c + 8], row1[c + 9]);
            Qh[kc][0] = *(uint32_t*)&a0;
            Qh[kc][1] = *(uint32_t*)&a1;
            Qh[kc][2] = *(uint32_t*)&a2;
            Qh[kc][3] = *(uint32_t*)&a3;
        }
    }
    __syncthreads();

    // ---- tile loader (K + V^T)
    auto load_tile = [&](int st, int k0) {
        uint32_t base = sbase + 4 * (st * STG);
#pragma unroll
        for (int i = 0; i < 4; ++i) {
            int idx = tid + i * NT;        // 32 rows x 16 chunks
            int r = idx >> 4, c = idx & 15;
            CP_ASYNC16F(base + (uint32_t)(KHo + r * KBSTR + c * 4) * 4,
                        &g_k2[b][k0 + r][c * 4]);
        }
        const __half* vt = &g_vT[b][k0 >> 5][0][0];
#pragma unroll
        for (int i = 0; i < 4; ++i) {
            int idx = tid + i * NT;        // 128 dims x 4 chunks
            int d = idx >> 2, c = idx & 3;
            CP_ASYNC16F(base + (uint32_t)(VTo + d * VTSTR + c * 4) * 4,
                        vt + (size_t)d * 32 + c * 8);
        }
    };

    load_tile(0, kbeg);
    CP_COMMIT();
    if (ntiles > 1) load_tile(1, kbeg + BK);
    CP_COMMIT();

    float o[16][4];
#pragma unroll
    for (int nc = 0; nc < 16; ++nc)
#pragma unroll
        for (int i = 0; i < 4; ++i) o[nc][i] = 0.f;
    float lsum0 = 0.f, lsum1 = 0.f;

    uint32_t* sp = (uint32_t*)&sm[P2w + wid * 16 * P2STR];
    const uint32_t spb = sbase + 4 * (uint32_t)(P2w + wid * 16 * P2STR);

    for (int kt = 0; kt < ntiles; ++kt) {
        const int k0 = kbeg + kt * BK;
        const int st = kt & 1;
        if (kt + 1 < ntiles)
            asm volatile("cp.async.wait_group 1;" ::: "memory");
        else
            asm volatile("cp.async.wait_group 0;" ::: "memory");
        __syncthreads();

        const uint32_t kfb = sbase + 4 * (uint32_t)(st * STG + KHo);
        const uint32_t vtb = sbase + 4 * (uint32_t)(st * STG + VTo);

        // ---- MMA1: S[16 x 32] per warp; B via ldmatrix.x4
        float s[4][4];
#pragma unroll
        for (int nc = 0; nc < 4; ++nc)
#pragma unroll
            for (int i = 0; i < 4; ++i) s[nc][i] = 0.f;
#pragma unroll
        for (int kc2 = 0; kc2 < 4; ++kc2) {
#pragma unroll
            for (int nc = 0; nc < 4; ++nc) {
                uint32_t b0, b1, b2, b3;
                uint32_t a = kfb +
                    4u * (uint32_t)((nc * 8 + lr) * KBSTR + kc2 * 16 + grp * 4);
                LDSM_X4(b0, b1, b2, b3, a);
                mma_fp16(s[nc], Qh[2 * kc2],     b0, b1);
                mma_fp16(s[nc], Qh[2 * kc2 + 1], b2, b3);
            }
        }

        // ---- mask + exp -> fp16 pairs; lsum from ROUNDED values
#pragma unroll
        for (int nc = 0; nc < 4; ++nc) {
            int c0 = k0 + nc * 8 + 2 * qd;
            bool v0 = c0 < kend, v1 = c0 + 1 < kend;
            float p0 = v0 ? __expf(s[nc][0]) : 0.f;
            float p1 = v1 ? __expf(s[nc][1]) : 0.f;
            float p2 = v0 ? __expf(s[nc][2]) : 0.f;
            float p3 = v1 ? __expf(s[nc][3]) : 0.f;
            __half2 h01 = __floats2half2_rn(p0, p1);
            __half2 h23 = __floats2half2_rn(p2, p3);
            float2 f01 = __half22float2(h01);
            float2 f23 = __half22float2(h23);
            lsum0 += f01.x + f01.y;
            lsum1 += f23.x + f23.y;
            sp[g * P2STR + nc * 4 + qd]       = *(uint32_t*)&h01;
            sp[(g + 8) * P2STR + nc * 4 + qd] = *(uint32_t*)&h23;
        }
        __syncwarp();

        // ---- PV: A-frags (P) + B-frags (V^T) via ldmatrix.x4
        uint32_t A0[4], A1[4];
        {
            uint32_t rbase = (uint32_t)(((grp & 1) * 8 + lr) * P2STR +
                                        (grp >> 1) * 4);
            LDSM_X4(A0[0], A0[1], A0[2], A0[3], spb + 4u * rbase);
            LDSM_X4(A1[0], A1[1], A1[2], A1[3], spb + 4u * (rbase + 8));
        }
#pragma unroll
        for (int nc = 0; nc < 16; ++nc) {
            uint32_t v0, v1, v2, v3;
            uint32_t a = vtb + 4u * (uint32_t)((nc * 8 + lr) * VTSTR + grp * 4);
            LDSM_X4(v0, v1, v2, v3, a);
            mma_fp16(o[nc], A0, v0, v1);
            mma_fp16(o[nc], A1, v2, v3);
        }
        __syncthreads();

        if (kt + 2 < ntiles) {
            load_tile(st, k0 + 2 * BK);
            CP_COMMIT();
        }
    }

    // ---- epilogue: fp16 partial O + fp32 l
    lsum0 += __shfl_xor_sync(0xffffffffu, lsum0, 1);
    lsum0 += __shfl_xor_sync(0xffffffffu, lsum0, 2);
    lsum1 += __shfl_xor_sync(0xffffffffu, lsum1, 1);
    lsum1 += __shfl_xor_sync(0xffffffffu, lsum1, 2);

    const int r0 = wid * 16 + g;
    __half* o0 = &g_pOh[b][qt][spl][r0][0];
    __half* o1 = &g_pOh[b][qt][spl][r0 + 8][0];
#pragma unroll
    for (int nc = 0; nc < 16; ++nc) {
        __half2 a = __floats2half2_rn(o[nc][0], o[nc][1]);
        __half2 c = __floats2half2_rn(o[nc][2], o[nc][3]);
        *(__half2*)&o0[nc * 8 + 2 * qd] = a;
        *(__half2*)&o1[nc * 8 + 2 * qd] = c;
    }
    if (qd == 0) {
        g_pl[b][qt][spl][r0]     = lsum0;
        g_pl[b][qt][spl][r0 + 8] = lsum1;
    }
}

// ---- combine: sum fp16 split partials + folded meanv for rows >= L ----
__global__ void __launch_bounds__(128)
combine_kernel(const int* __restrict__ elen, float* __restrict__ out) {
    __shared__ alignas(16) float mv[DIM];
    const int b   = blockIdx.y;
    const int qt  = blockIdx.x;
    const int tid = threadIdx.x;
    const int r     = tid >> 1;           // 0..63
    const int dhalf = (tid & 1) * 64;
    const int row   = qt * BQ + r;
    const int L     = elen[b];

    const bool need_mean = (qt * BQ + BQ > L);
    if (need_mean) {
        if (tid < DIM) {
            float s = 0.f;
#pragma unroll
            for (int c = 0; c < 16; ++c) s += g_partial[b][c][tid];
            mv[tid] = s * (1.0f / SEQ);
        }
        __syncthreads();
    }

    float4* op = (float4*)(out + ((size_t)b * SEQ + row) * DIM + dhalf);

    if (row >= L) {
#pragma unroll
        for (int j = 0; j < 16; ++j) op[j] = *(float4*)&mv[dhalf + j * 4];
        return;
    }

    const int nspl = (L + SPLITK - 1) / SPLITK;
    float lsum = 0.f;
    float acc[64];
#pragma unroll
    for (int j = 0; j < 64; ++j) acc[j] = 0.f;

    for (int s = 0; s < nspl; ++s) {
        lsum += g_pl[b][qt][s][r];
        const uint4* po = (const uint4*)(&g_pOh[b][qt][s][r][dhalf]);
#pragma unroll
        for (int j = 0; j < 8; ++j) {
            uint4 t = po[j];
            float2 f0 = __half22float2(*(__half2*)&t.x);
            float2 f1 = __half22float2(*(__half2*)&t.y);
            float2 f2 = __half22float2(*(__half2*)&t.z);
            float2 f3 = __half22float2(*(__half2*)&t.w);
            acc[8*j+0] += f0.x; acc[8*j+1] += f0.y;
            acc[8*j+2] += f1.x; acc[8*j+3] += f1.y;
            acc[8*j+4] += f2.x; acc[8*j+5] += f2.y;
            acc[8*j+6] += f3.x; acc[8*j+7] += f3.y;
        }
    }
    float inv = 1.0f / lsum;
#pragma unroll
    for (int j = 0; j < 16; ++j)
        op[j] = make_float4(acc[4*j] * inv, acc[4*j+1] * inv,
                            acc[4*j+2] * inv, acc[4*j+3] * inv);
}

extern "C" void kernel_launch(void* const* d_in, const int* in_sizes, int n_in,
                              void* d_out, int out_size) {
    const float* q  = (const float*)d_in[0];
    const float* k  = (const float*)d_in[1];
    const float* v  = (const float*)d_in[2];
    const int*   el = (const int*)d_in[3];
    float*       out = (float*)d_out;

    cudaFuncSetAttribute(attn_kernel,
                         cudaFuncAttributeMaxDynamicSharedMemorySize, SMEM_BYTES);

    prep_kernel<<<dim3(144, BATCH), 256>>>(k, v);
    attn_kernel<<<dim3(QT, BATCH, MAXSPL), NT, SMEM_BYTES>>>(q, el);
    combine_kernel<<<dim3(QT, BATCH), 128>>>(el, out);
}

// round 16
// speedup vs baseline: 1.1704x; 1.0918x over previous
#include <cuda_runtime.h>
#include <cuda_fp16.h>
#include <cstdint>

#define BATCH 8
#define SEQ   2048
#define DIM   128
#define BQ    64               // queries per CTA (4 warps x 16 rows)
#define BK    32               // keys per inner tile (3-stage pipeline)
#define NT    128
#define QT    (SEQ / BQ)       // 32
#define SPLITK 512
#define MAXSPL (SEQ / SPLITK)  // 4

// strides (32-bit words)
#define KBSTR 68    // fp16 K rows: 64 u32 payload (banks 4g+qd distinct)
#define V2STR 136   // V fp16-pair rows (banks 8qd+g distinct)
#define QSTGS 132   // Q fp32 staging stride

// smem: stage = K(32*68) + V2(16*136) = 4352 words; 3 stages
#define STG   4352
#define KHo   0
#define V2o   (32 * KBSTR)            // 2176
#define SMEM_WORDS (3 * STG)          // 13056
#define SMEM_BYTES (SMEM_WORDS * 4)   // 52224 -> 4 CTAs/SM (209 KB)

// ---- scratch ----
__device__ alignas(16) uint32_t g_k2[BATCH][SEQ][64];        // half2 dim-pairs
__device__ alignas(16) uint32_t g_v2[BATCH][SEQ / 2][DIM];   // half2 key-pairs
__device__ float g_partial[BATCH][16][DIM];
__device__ alignas(16) __half g_pOh[BATCH][QT][MAXSPL][BQ][DIM];
__device__ float g_pl[BATCH][QT][MAXSPL][BQ];

// ---- helpers ----
__device__ __forceinline__ uint32_t smem_u32(const void* p) {
    uint32_t a;
    asm("{ .reg .u64 t; cvta.to.shared.u64 t, %1; cvt.u32.u64 %0, t; }"
        : "=r"(a) : "l"(p));
    return a;
}
__device__ __forceinline__ void mma_fp16(float* c, const uint32_t* a,
                                         uint32_t b0, uint32_t b1) {
    asm volatile(
        "mma.sync.aligned.m16n8k16.row.col.f32.f16.f16.f32 "
        "{%0,%1,%2,%3}, {%4,%5,%6,%7}, {%8,%9}, {%0,%1,%2,%3};"
        : "+f"(c[0]), "+f"(c[1]), "+f"(c[2]), "+f"(c[3])
        : "r"(a[0]), "r"(a[1]), "r"(a[2]), "r"(a[3]), "r"(b0), "r"(b1));
}
#define CP_ASYNC16F(dst, src) \
    asm volatile("cp.async.ca.shared.global [%0], [%1], 16;" \
                 :: "r"(dst), "l"(src) : "memory")
#define CP_COMMIT() asm volatile("cp.async.commit_group;" ::: "memory")

// ---- prep: K -> fp16 dim-pairs; V -> fp16 key-pairs; V chunk sums ----
__global__ void __launch_bounds__(256)
prep_kernel(const float* __restrict__ k, const float* __restrict__ v) {
    const int b = blockIdx.y, x = blockIdx.x, tid = threadIdx.x;
    if (x < 64) {
        // K convert: rows [32x, 32x+32)
        const float* kb = k + ((size_t)b * SEQ + 32 * x) * DIM;
#pragma unroll
        for (int i = 0; i < 4; ++i) {
            int idx = tid + i * 256;      // 32 rows x 32 float4
            int r = idx >> 5, c4 = idx & 31;
            float4 t = ((const float4*)(kb + (size_t)r * DIM))[c4];
            __half2 h01 = __floats2half2_rn(t.x, t.y);
            __half2 h23 = __floats2half2_rn(t.z, t.w);
            *(uint2*)&g_k2[b][32 * x + r][c4 * 2] =
                make_uint2(*(uint32_t*)&h01, *(uint32_t*)&h23);
        }
    } else if (x < 96) {
        // V pairs: keypairs [32(x-64), +32)
        int kp0 = 32 * (x - 64);
        const float* vb = v + ((size_t)b * SEQ + 2 * kp0) * DIM;
#pragma unroll
        for (int i = 0; i < 4; ++i) {
            int idx = tid + i * 256;      // 32 pairs x 32 float4-cols
            int kp = idx >> 5, c4 = idx & 31;
            float4 a = ((const float4*)(vb + (size_t)(2 * kp) * DIM))[c4];
            float4 c = ((const float4*)(vb + (size_t)(2 * kp + 1) * DIM))[c4];
            __half2 p0 = __floats2half2_rn(a.x, c.x);
            __half2 p1 = __floats2half2_rn(a.y, c.y);
            __half2 p2 = __floats2half2_rn(a.z, c.z);
            __half2 p3 = __floats2half2_rn(a.w, c.w);
            uint4 pk = make_uint4(*(uint32_t*)&p0, *(uint32_t*)&p1,
                                  *(uint32_t*)&p2, *(uint32_t*)&p3);
            *(uint4*)&g_v2[b][kp0 + kp][c4 * 4] = pk;
        }
    } else {
        // V chunk sums: chunk c = x - 96, rows [128c, 128c+128)
        __shared__ float vs[2][DIM];
        int c = x - 96;
        int d = tid & 127, h = tid >> 7;
        const float* vp = v + ((size_t)b * SEQ + 128 * c + 64 * h) * DIM + d;
        float s = 0.f;
#pragma unroll 8
        for (int r = 0; r < 64; ++r) s += vp[(size_t)r * DIM];
        vs[h][d] = s;
        __syncthreads();
        if (tid < DIM) g_partial[b][c][tid] = vs[0][tid] + vs[1][tid];
    }
}

// ---- fp16 flash attn: register-P, 3-stage pipeline, 1 barrier/tile ----
__global__ void __launch_bounds__(NT, 4)
attn_kernel(const float* __restrict__ q, const int* __restrict__ elen) {
    extern __shared__ float sm[];
    const int b    = blockIdx.y;
    const int qt   = blockIdx.x;
    const int spl  = blockIdx.z;
    const int q0   = qt * BQ;
    const int L    = elen[b];
    const int kbeg = spl * SPLITK;
    const int tid  = threadIdx.x;
    const int wid  = tid >> 5;
    const int lane = tid & 31;
    const int g    = lane >> 2;
    const int qd   = lane & 3;

    if (q0 >= L || kbeg >= L) return;
    const int kend = min(kbeg + SPLITK, L);
    const int ntiles = (kend - kbeg + BK - 1) / BK;

    const uint32_t sbase = smem_u32(sm);
    const float* qb = q + ((size_t)b * SEQ + q0) * DIM;

    // ---- stage Q fp32 (scaled)
    const float scale = 0.08838834764831845f;
#pragma unroll
    for (int i = 0; i < 16; ++i) {
        int idx = tid + i * NT;
        int r = idx >> 5, c4 = idx & 31;
        float4 t = ((const float4*)(qb + (size_t)r * DIM))[c4];
        t.x *= scale; t.y *= scale; t.z *= scale; t.w *= scale;
        *(float4*)&sm[r * QSTGS + c4 * 4] = t;
    }
    __syncthreads();

    // ---- resident fp16 Q fragments
    uint32_t Qh[8][4];
    {
        const int r0 = wid * 16 + g;
        const float* row0 = &sm[r0 * QSTGS];
        const float* row1 = &sm[(r0 + 8) * QSTGS];
#pragma unroll
        for (int kc = 0; kc < 8; ++kc) {
            int c = kc * 16 + 2 * qd;
            __half2 a0 = __floats2half2_rn(row0[c],     row0[c + 1]);
            __half2 a1 = __floats2half2_rn(row1[c],     row1[c + 1]);
            __half2 a2 = __floats2half2_rn(row0[c + 8], row0[c + 9]);
            __half2 a3 = __floats2half2_rn(row1[c + 8], row1[c + 9]);
            Qh[kc][0] = *(uint32_t*)&a0;
            Qh[kc][1] = *(uint32_t*)&a1;
            Qh[kc][2] = *(uint32_t*)&a2;
            Qh[kc][3] = *(uint32_t*)&a3;
        }
    }
    __syncthreads();

    // ---- tile loader: 32 keys -> stage st (0..2)
    auto load_tile = [&](int st, int k0) {
        uint32_t base = sbase + 4 * (st * STG);
#pragma unroll
        for (int i = 0; i < 4; ++i) {
            int idx = tid + i * NT;        // 32 rows x 16 chunks
            int r = idx >> 4, c = idx & 15;
            CP_ASYNC16F(base + (uint32_t)(KHo + r * KBSTR + c * 4) * 4,
                        &g_k2[b][k0 + r][c * 4]);
        }
#pragma unroll
        for (int i = 0; i < 4; ++i) {
            int idx = tid + i * NT;        // 16 pair-rows x 32 chunks
            int r = idx >> 5, c4 = idx & 31;
            CP_ASYNC16F(base + (uint32_t)(V2o + r * V2STR + c4 * 4) * 4,
                        &g_v2[b][(k0 >> 1) + r][c4 * 4]);
        }
    };

    load_tile(0, kbeg);
    CP_COMMIT();
    if (ntiles > 1) { load_tile(1, kbeg + BK); CP_COMMIT(); }

    float o[16][4];
#pragma unroll
    for (int nc = 0; nc < 16; ++nc)
#pragma unroll
        for (int i = 0; i < 4; ++i) o[nc][i] = 0.f;
    float lsum0 = 0.f, lsum1 = 0.f;

    for (int kt = 0; kt < ntiles; ++kt) {
        const int k0 = kbeg + kt * BK;
        const int st = kt % 3;
        if (kt + 1 < ntiles)
            asm volatile("cp.async.wait_group 1;" ::: "memory");
        else
            asm volatile("cp.async.wait_group 0;" ::: "memory");
        __syncthreads();   // stage kt visible; stage (kt+2)%3 == (kt-1)%3 free

        if (kt + 2 < ntiles) {
            load_tile((kt + 2) % 3, k0 + 2 * BK);
            CP_COMMIT();
        }

        const uint32_t* k2  = (const uint32_t*)&sm[st * STG + KHo];
        const uint32_t* sv2 = (const uint32_t*)&sm[st * STG + V2o];

        // ---- MMA1: S[16 x 32] per warp
        float s[4][4];
#pragma unroll
        for (int nc = 0; nc < 4; ++nc)
#pragma unroll
            for (int i = 0; i < 4; ++i) s[nc][i] = 0.f;
#pragma unroll
        for (int kc = 0; kc < 8; ++kc) {
#pragma unroll
            for (int nc = 0; nc < 4; ++nc) {
                int bse = (nc * 8 + g) * KBSTR + kc * 8 + qd;
                mma_fp16(s[nc], Qh[kc], k2[bse], k2[bse + 4]);
            }
        }

        // ---- mask + exp -> fp16 pairs IN REGISTERS; lsum from ROUNDED values
        uint32_t ph0[4], ph1[4];   // h01[nc] (row g), h23[nc] (row g+8)
#pragma unroll
        for (int nc = 0; nc < 4; ++nc) {
            int c0 = k0 + nc * 8 + 2 * qd;
            bool v0 = c0 < kend, v1 = c0 + 1 < kend;
            float p0 = v0 ? __expf(s[nc][0]) : 0.f;
            float p1 = v1 ? __expf(s[nc][1]) : 0.f;
            float p2 = v0 ? __expf(s[nc][2]) : 0.f;
            float p3 = v1 ? __expf(s[nc][3]) : 0.f;
            __half2 h01 = __floats2half2_rn(p0, p1);
            __half2 h23 = __floats2half2_rn(p2, p3);
            float2 f01 = __half22float2(h01);
            float2 f23 = __half22float2(h23);
            lsum0 += f01.x + f01.y;
            lsum1 += f23.x + f23.y;
            ph0[nc] = *(uint32_t*)&h01;
            ph1[nc] = *(uint32_t*)&h23;
        }

        // ---- PV: A-frags are exactly the local P registers (lane algebra)
#pragma unroll
        for (int kc = 0; kc < 2; ++kc) {
            uint32_t A[4] = {ph0[2 * kc], ph1[2 * kc],
                             ph0[2 * kc + 1], ph1[2 * kc + 1]};
#pragma unroll
            for (int nc = 0; nc < 16; ++nc) {
                int col = nc * 8 + g;
                uint32_t b0 = sv2[(kc * 8 + qd) * V2STR + col];
                uint32_t b1 = sv2[(kc * 8 + 4 + qd) * V2STR + col];
                mma_fp16(o[nc], A, b0, b1);
            }
        }
        // no bottom barrier: next iteration's top barrier covers stage reuse
    }

    // ---- epilogue: fp16 partial O + fp32 l
    lsum0 += __shfl_xor_sync(0xffffffffu, lsum0, 1);
    lsum0 += __shfl_xor_sync(0xffffffffu, lsum0, 2);
    lsum1 += __shfl_xor_sync(0xffffffffu, lsum1, 1);
    lsum1 += __shfl_xor_sync(0xffffffffu, lsum1, 2);

    const int r0 = wid * 16 + g;
    __half* o0 = &g_pOh[b][qt][spl][r0][0];
    __half* o1 = &g_pOh[b][qt][spl][r0 + 8][0];
#pragma unroll
    for (int nc = 0; nc < 16; ++nc) {
        __half2 a = __floats2half2_rn(o[nc][0], o[nc][1]);
        __half2 c = __floats2half2_rn(o[nc][2], o[nc][3]);
        *(__half2*)&o0[nc * 8 + 2 * qd] = a;
        *(__half2*)&o1[nc * 8 + 2 * qd] = c;
    }
    if (qd == 0) {
        g_pl[b][qt][spl][r0]     = lsum0;
        g_pl[b][qt][spl][r0 + 8] = lsum1;
    }
}

// ---- combine (256 thr): sum fp16 split partials + meanv for rows >= L ----
__global__ void __launch_bounds__(256)
combine_kernel(const int* __restrict__ elen, float* __restrict__ out) {
    __shared__ alignas(16) float mv[DIM];
    const int b   = blockIdx.y;
    const int qt  = blockIdx.x;
    const int tid = threadIdx.x;
    const int r     = tid >> 2;           // 0..63
    const int dq    = (tid & 3) * 32;     // 32-float quarter
    const int row   = qt * BQ + r;
    const int L     = elen[b];

    const bool need_mean = (qt * BQ + BQ > L);
    if (need_mean) {
        if (tid < DIM) {
            float s = 0.f;
#pragma unroll
            for (int c = 0; c < 16; ++c) s += g_partial[b][c][tid];
            mv[tid] = s * (1.0f / SEQ);
        }
        __syncthreads();
    }

    float4* op = (float4*)(out + ((size_t)b * SEQ + row) * DIM + dq);

    if (row >= L) {
#pragma unroll
        for (int j = 0; j < 8; ++j) op[j] = *(float4*)&mv[dq + j * 4];
        return;
    }

    const int nspl = (L + SPLITK - 1) / SPLITK;
    float lsum = 0.f;
    float acc[32];
#pragma unroll
    for (int j = 0; j < 32; ++j) acc[j] = 0.f;

    for (int s = 0; s < nspl; ++s) {
        lsum += g_pl[b][qt][s][r];
        const uint4* po = (const uint4*)(&g_pOh[b][qt][s][r][dq]);
#pragma unroll
        for (int j = 0; j < 4; ++j) {     // 4 x uint4 = 32 halves
            uint4 t = po[j];
            float2 f0 = __half22float2(*(__half2*)&t.x);
            float2 f1 = __half22float2(*(__half2*)&t.y);
            float2 f2 = __half22float2(*(__half2*)&t.z);
            float2 f3 = __half22float2(*(__half2*)&t.w);
            acc[8*j+0] += f0.x; acc[8*j+1] += f0.y;
            acc[8*j+2] += f1.x; acc[8*j+3] += f1.y;
            acc[8*j+4] += f2.x; acc[8*j+5] += f2.y;
            acc[8*j+6] += f3.x; acc[8*j+7] += f3.y;
        }
    }
    float inv = 1.0f / lsum;
#pragma unroll
    for (int j = 0; j < 8; ++j)
        op[j] = make_float4(acc[4*j] * inv, acc[4*j+1] * inv,
                            acc[4*j+2] * inv, acc[4*j+3] * inv);
}

extern "C" void kernel_launch(void* const* d_in, const int* in_sizes, int n_in,
                              void* d_out, int out_size) {
    const float* q  = (const float*)d_in[0];
    const float* k  = (const float*)d_in[1];
    const float* v  = (const float*)d_in[2];
    const int*   el = (const int*)d_in[3];
    float*       out = (float*)d_out;

    cudaFuncSetAttribute(attn_kernel,
                         cudaFuncAttributeMaxDynamicSharedMemorySize, SMEM_BYTES);

    prep_kernel<<<dim3(112, BATCH), 256>>>(k, v);
    attn_kernel<<<dim3(QT, BATCH, MAXSPL), NT, SMEM_BYTES>>>(q, el);
    combine_kernel<<<dim3(QT, BATCH), 256>>>(el, out);
}